// round 11
// baseline (speedup 1.0000x reference)
#include <cuda_runtime.h>
#include <cuda_bf16.h>

// FeaturesLinear: out[seg] = sum_t (weight[ids[t]] * ratings[t]) + bias
// ids: int32[N], ratings: f32[N], segs: int32[N] (sorted), weight: f32[V,16],
// bias: f32[16], out: f32[batch,16].  N = 819200 (multiple of 32).
//
// PDL: fl_main overlaps its gather prelude with fl_init_out; it only
// synchronizes on init completion right before the first atomic flush.

#define DIM 16
#define T_PER_THREAD 4   // tokens per thread

__device__ __forceinline__ float4 ldg_wt(const float4* p, unsigned long long pol) {
    float4 v;
    asm("ld.global.nc.L2::cache_hint.v4.f32 {%0,%1,%2,%3}, [%4], %5;"
        : "=f"(v.x), "=f"(v.y), "=f"(v.z), "=f"(v.w)
        : "l"(p), "l"(pol));
    return v;
}
__device__ __forceinline__ int4 ldg_meta_i4(const int4* p, unsigned long long pol) {
    int4 v;
    asm("ld.global.nc.L2::cache_hint.v4.u32 {%0,%1,%2,%3}, [%4], %5;"
        : "=r"(v.x), "=r"(v.y), "=r"(v.z), "=r"(v.w)
        : "l"(p), "l"(pol));
    return v;
}
__device__ __forceinline__ float4 ldg_meta_f4(const float4* p, unsigned long long pol) {
    float4 v;
    asm("ld.global.nc.L2::cache_hint.v4.f32 {%0,%1,%2,%3}, [%4], %5;"
        : "=f"(v.x), "=f"(v.y), "=f"(v.z), "=f"(v.w)
        : "l"(p), "l"(pol));
    return v;
}
// One-instruction float4 global reduction (sm_100+).
__device__ __forceinline__ void red_add_v4(float* o, float4 v) {
    asm volatile("red.global.v4.f32.add [%0], {%1,%2,%3,%4};"
                 :: "l"(o), "f"(v.x), "f"(v.y), "f"(v.z), "f"(v.w) : "memory");
}

__global__ void fl_init_out(float4* __restrict__ out,
                            const float4* __restrict__ bias4,
                            int out_quads) {
    int i = blockIdx.x * blockDim.x + threadIdx.x;
    if (i < out_quads) out[i] = __ldg(&bias4[i & 3]);
    // Allow the dependent fl_main grid to launch as soon as stores are issued.
    cudaTriggerProgrammaticLaunchCompletion();
}

// Lane layout: slot = lane & 3 (which float4 of the 16-float row),
// tokGroup = lane >> 2 (0..7). Thread handles 4 consecutive tokens;
// a warp covers 32 consecutive tokens.
__global__ __launch_bounds__(256)
void fl_main(const int*   __restrict__ ids,
             const float* __restrict__ ratings,
             const int*   __restrict__ segs,
             const float4* __restrict__ weight4,
             float*       __restrict__ out,
             int n) {
    const int lane     = threadIdx.x & 31;
    const int slot     = lane & 3;
    const int tokGroup = lane >> 2;
    const int warpsPerBlock = blockDim.x >> 5;
    const int warpId   = blockIdx.x * warpsPerBlock + (threadIdx.x >> 5);

    const int base = warpId * 32 + tokGroup * T_PER_THREAD;
    if (base >= n) { cudaGridDependencySynchronize(); return; }

    unsigned long long polWt, polMeta;
    asm("createpolicy.fractional.L2::evict_last.b64 %0, 0.75;"  : "=l"(polWt));
    asm("createpolicy.fractional.L2::evict_first.b64 %0, 1.0;" : "=l"(polMeta));

    // ---- metadata for 4 tokens (L1-cached broadcast; L2 evict_first)
    int4   idv = ldg_meta_i4((const int4*)  (ids     + base), polMeta);
    float4 rv  = ldg_meta_f4((const float4*)(ratings + base), polMeta);
    int4   sv  = ldg_meta_i4((const int4*)  (segs    + base), polMeta);

    const int   id[4] = {idv.x, idv.y, idv.z, idv.w};
    const float r [4] = {rv.x,  rv.y,  rv.z,  rv.w};
    const int   sg[4] = {sv.x,  sv.y,  sv.z,  sv.w};

    // ---- issue all 4 independent row gathers up front (MLP = 4)
    float4 w[4];
    #pragma unroll
    for (int k = 0; k < T_PER_THREAD; k++)
        w[k] = ldg_wt(&weight4[(size_t)id[k] * 4 + slot], polWt);

    // Init kernel's stores must be visible before any atomic flush below.
    // (Gathers above are already in flight; this only orders vs. init grid.)
    cudaGridDependencySynchronize();

    // ---- thread-serial accumulation with flush on segment boundary
    float4 acc;
    acc.x = w[0].x * r[0]; acc.y = w[0].y * r[0];
    acc.z = w[0].z * r[0]; acc.w = w[0].w * r[0];

    #pragma unroll
    for (int k = 1; k < T_PER_THREAD; k++) {
        if (sg[k] != sg[k - 1]) {
            red_add_v4(out + (size_t)sg[k - 1] * DIM + slot * 4, acc);
            acc.x = acc.y = acc.z = acc.w = 0.f;
        }
        acc.x += w[k].x * r[k]; acc.y += w[k].y * r[k];
        acc.z += w[k].z * r[k]; acc.w += w[k].w * r[k];
    }

    // ---- cross-lane segmented suffix reduction on trailing partials.
    // Trailing keys are monotone across the warp (sorted segs), so the
    // strided conditional add is an exact segmented reduction.
    int seg = sg[T_PER_THREAD - 1];
    #pragma unroll
    for (int off = 4; off <= 16; off <<= 1) {
        int   oseg = __shfl_down_sync(0xffffffffu, seg, off);
        float ox   = __shfl_down_sync(0xffffffffu, acc.x, off);
        float oy   = __shfl_down_sync(0xffffffffu, acc.y, off);
        float oz   = __shfl_down_sync(0xffffffffu, acc.z, off);
        float ow   = __shfl_down_sync(0xffffffffu, acc.w, off);
        if ((lane + off) < 32 && oseg == seg) {
            acc.x += ox; acc.y += oy; acc.z += oz; acc.w += ow;
        }
    }

    const int  pseg = __shfl_up_sync(0xffffffffu, seg, 4);
    const bool head = (tokGroup == 0) || (pseg != seg);

    if (head) {
        red_add_v4(out + (size_t)seg * DIM + slot * 4, acc);
    }
}

extern "C" void kernel_launch(void* const* d_in, const int* in_sizes, int n_in,
                              void* d_out, int out_size) {
    const int*   ids     = (const int*)  d_in[0];
    const float* ratings = (const float*)d_in[1];
    const int*   segs    = (const int*)  d_in[2];
    // d_in[3] = batch_size scalar (unused)
    const float* weight  = (const float*)d_in[4];
    const float* bias    = (const float*)d_in[5];
    float*       out     = (float*)d_out;

    const int n = in_sizes[0];

    // Init output with bias (vectorized).
    {
        int quads   = out_size / 4;
        int threads = 256;
        int blocks  = (quads + threads - 1) / threads;
        fl_init_out<<<blocks, threads>>>((float4*)out, (const float4*)bias, quads);
    }

    // Main gather + segmented reduce, launched with programmatic stream
    // serialization so its prelude overlaps the init kernel.
    {
        int warps   = (n + 31) / 32;
        int threads = 256;
        int blocks  = (warps + 7) / 8;

        cudaLaunchConfig_t cfg = {};
        cfg.gridDim  = dim3(blocks, 1, 1);
        cfg.blockDim = dim3(threads, 1, 1);
        cfg.dynamicSmemBytes = 0;
        cfg.stream = 0;
        cudaLaunchAttribute attrs[1];
        attrs[0].id = cudaLaunchAttributeProgrammaticStreamSerialization;
        attrs[0].val.programmaticStreamSerializationAllowed = 1;
        cfg.attrs = attrs;
        cfg.numAttrs = 1;

        cudaLaunchKernelEx(&cfg, fl_main, ids, ratings, segs,
                           (const float4*)weight, out, n);
    }
}